// round 17
// baseline (speedup 1.0000x reference)
#include <cuda_runtime.h>
#include <cuda_fp16.h>
#include <math.h>
#include <stdint.h>

// Problem constants
#define TOK   8192        // B*N
#define DIMC  1024
#define EXPC  7168
#define CINC  5120
#define NHC   16
#define HDC   64
#define SEQC  1024
#define NB    8
#define BH    (NB * NHC)  // 128 batch-heads

#define LOG2E 1.44269504088896340736f

// ---------------------------------------------------------------------------
// Scratch (device globals; allocation-free)
// ---------------------------------------------------------------------------
__device__ __half g_yh[(size_t)TOK * 2 * DIMC];               // k,v pre-LN fp16

__device__ __half g_xn[(size_t)TOK * DIMC];
__device__ __half g_we[(size_t)EXPC * DIMC];
__device__ __half g_wc[(size_t)2 * DIMC * CINC];
__device__ __half g_h [(size_t)TOK * CINC];

// attention operands (per-head [bh][seq][hd]; all single fp16)
__device__ __half g_q[(size_t)BH * SEQC * HDC];
__device__ __half g_k[(size_t)BH * SEQC * HDC];
__device__ __half g_v[(size_t)BH * SEQC * HDC];

// expert grouping
__device__ int g_cnt[4];
__device__ int g_goff[4];
__device__ int g_perm[TOK];

// ---------------------------------------------------------------------------
// PTX helpers
// ---------------------------------------------------------------------------
__device__ __forceinline__ uint32_t smem_u32(const void* p) {
    uint32_t a;
    asm("{ .reg .u64 t; cvta.to.shared.u64 t, %1; cvt.u32.u64 %0, t; }" : "=r"(a) : "l"(p));
    return a;
}
__device__ __forceinline__ void ldsm4(uint32_t* r, uint32_t a) {
    asm volatile("ldmatrix.sync.aligned.m8n8.x4.shared.b16 {%0,%1,%2,%3}, [%4];"
                 : "=r"(r[0]), "=r"(r[1]), "=r"(r[2]), "=r"(r[3]) : "r"(a));
}
__device__ __forceinline__ void ldsm4t(uint32_t* r, uint32_t a) {
    asm volatile("ldmatrix.sync.aligned.m8n8.x4.trans.shared.b16 {%0,%1,%2,%3}, [%4];"
                 : "=r"(r[0]), "=r"(r[1]), "=r"(r[2]), "=r"(r[3]) : "r"(a));
}
__device__ __forceinline__ void mma16816h(float* c, const uint32_t* a, const uint32_t* b) {
    asm volatile("mma.sync.aligned.m16n8k16.row.col.f32.f16.f16.f32 "
                 "{%0,%1,%2,%3}, {%4,%5,%6,%7}, {%8,%9}, {%0,%1,%2,%3};"
                 : "+f"(c[0]), "+f"(c[1]), "+f"(c[2]), "+f"(c[3])
                 : "r"(a[0]), "r"(a[1]), "r"(a[2]), "r"(a[3]), "r"(b[0]), "r"(b[1]));
}
__device__ __forceinline__ void cpa16(uint32_t s, const void* g) {
    asm volatile("cp.async.cg.shared.global [%0], [%1], 16;" :: "r"(s), "l"(g));
}
#define CP_COMMIT() asm volatile("cp.async.commit_group;")
#define CP_WAIT1()  asm volatile("cp.async.wait_group 1;")
#define CP_WAIT0()  asm volatile("cp.async.wait_group 0;")

#define SWZ(o) ((o) ^ (((o) >> 3) & 0x70))

__device__ __forceinline__ uint32_t pack_h2(__half a, __half b) {
    __half2 v(a, b);
    return *(uint32_t*)&v;
}
__device__ __forceinline__ float gelu1(float x) {
    return 0.5f * x * (1.f + erff(x * 0.70710678118654752f));
}

#define GOA  0
#define GOB  16384
#define GBUF 32768
#define GSM  (1024 + 3 * GBUF)    // 99328

// ---------------------------------------------------------------------------
// Expand GEMM (grouped, plain fp16), 256 thr, 8 warps (2m x 4n), warp 64x32.
// Single barrier per K-chunk (3-stage buffer; prefetch issued post-barrier).
// ---------------------------------------------------------------------------
__global__ void __launch_bounds__(256, 2)
expand_kernel(const float* __restrict__ mlpb) {
    const int e = 3 - blockIdx.z;
    const int cnt  = g_cnt[e];
    const int goff = g_goff[e];
    const int m0 = blockIdx.y * 128;
    if (m0 >= cnt) return;
    const int K  = 128 << e;
    const int n0 = blockIdx.x * 128;

    extern __shared__ char smem_raw[];
    uint32_t sb0 = smem_u32(smem_raw);
    sb0 = (sb0 + 1023u) & ~1023u;
    int* tok = (int*)(smem_raw + (sb0 - smem_u32(smem_raw)));
    uint32_t sb = sb0 + 1024u;

    const int tid  = threadIdx.x;
    const int lane = tid & 31;
    const int wid  = tid >> 5;
    const int wm = wid & 1;
    const int wn = wid >> 1;

    if (tid < 128) {
        int gr = m0 + tid;
        tok[tid] = g_perm[goff + ((gr < cnt) ? gr : 0)];
    }
    __syncthreads();

    const __half* BB = g_we + (size_t)n0 * DIMC;
    const int NC = K / 64;

    auto load_chunk = [&](int c) {
        uint32_t bufb = sb + (uint32_t)(c % 3) * GBUF;
        int k0 = c * 64;
#pragma unroll
        for (int it = 0; it < 4; it++) {
            int i = tid + it * 256;
            int r = i >> 3, kg = i & 7;
            const __half* src = g_xn + (size_t)tok[r] * DIMC + k0 + kg * 8;
            cpa16(bufb + GOA + SWZ(r * 128 + kg * 16), src);
        }
#pragma unroll
        for (int it = 0; it < 4; it++) {
            int i = tid + it * 256;
            int r = i >> 3, kg = i & 7;
            const __half* src = BB + (size_t)r * DIMC + k0 + kg * 8;
            cpa16(bufb + GOB + SWZ(r * 128 + kg * 16), src);
        }
        CP_COMMIT();
    };

    load_chunk(0);
    if (NC > 1) load_chunk(1);

    float acc[4][4][4];
#pragma unroll
    for (int i = 0; i < 4; i++)
#pragma unroll
        for (int j = 0; j < 4; j++)
#pragma unroll
            for (int k = 0; k < 4; k++) acc[i][j][k] = 0.f;

    const int a_r16 = lane & 15;
    const int a_kb  = (lane >> 4) * 16;
    const int b_r8  = ((lane >> 4) << 3) + (lane & 7);
    const int b_kb  = ((lane >> 3) & 1) * 16;

    for (int c = 0; c < NC; c++) {
        if (c < NC - 1) CP_WAIT1(); else CP_WAIT0();
        __syncthreads();
        if (c + 2 < NC) load_chunk(c + 2);

        uint32_t bufb = sb + (uint32_t)(c % 3) * GBUF;
#pragma unroll
        for (int kk = 0; kk < 4; kk++) {
            int kb = kk * 32;
            uint32_t ah[4][4];
#pragma unroll
            for (int mt = 0; mt < 4; mt++) {
                int r = wm * 64 + mt * 16 + a_r16;
                uint32_t off = (uint32_t)(r * 128) + (uint32_t)((kb + a_kb) ^ ((r & 7) << 4));
                ldsm4(ah[mt], bufb + GOA + off);
            }
#pragma unroll
            for (int ntp = 0; ntp < 2; ntp++) {
                int r = wn * 32 + ntp * 16 + b_r8;
                uint32_t off = (uint32_t)(r * 128) + (uint32_t)((kb + b_kb) ^ ((r & 7) << 4));
                uint32_t bf[4];
                ldsm4(bf, bufb + GOB + off);
#pragma unroll
                for (int mt = 0; mt < 4; mt++) {
                    mma16816h(acc[mt][2 * ntp],     ah[mt], bf);
                    mma16816h(acc[mt][2 * ntp + 1], ah[mt], bf + 2);
                }
            }
        }
    }

    const int g = lane >> 2, t4 = lane & 3;

#pragma unroll
    for (int mt = 0; mt < 4; mt++) {
        int r0 = wm * 64 + mt * 16 + g;
        int r1 = r0 + 8;
        int tk0 = tok[r0], tk1 = tok[r1];
        bool ok0 = (m0 + r0) < cnt, ok1 = (m0 + r1) < cnt;
        if (n0 < 1024) {
#pragma unroll
            for (int nt = 0; nt < 4; nt++) {
                int d = n0 + wn * 32 + nt * 8 + t4 * 2;
                int h = d >> 6, hd = d & 63;
                const float QS = 0.125f * LOG2E;
                if (ok0) {
                    size_t o = ((size_t)((tk0 >> 10) * NHC + h) * SEQC + (tk0 & 1023)) * HDC + hd;
                    *(uint32_t*)(g_q + o) = pack_h2(__float2half_rn(acc[mt][nt][0] * QS),
                                                   __float2half_rn(acc[mt][nt][1] * QS));
                }
                if (ok1) {
                    size_t o = ((size_t)((tk1 >> 10) * NHC + h) * SEQC + (tk1 & 1023)) * HDC + hd;
                    *(uint32_t*)(g_q + o) = pack_h2(__float2half_rn(acc[mt][nt][2] * QS),
                                                   __float2half_rn(acc[mt][nt][3] * QS));
                }
            }
        } else if (n0 < 3072) {
#pragma unroll
            for (int nt = 0; nt < 4; nt++) {
                int col = n0 - 1024 + wn * 32 + nt * 8 + t4 * 2;
                if (ok0) *(uint32_t*)(g_yh + (size_t)tk0 * 2048 + col) =
                    pack_h2(__float2half_rn(acc[mt][nt][0]), __float2half_rn(acc[mt][nt][1]));
                if (ok1) *(uint32_t*)(g_yh + (size_t)tk1 * 2048 + col) =
                    pack_h2(__float2half_rn(acc[mt][nt][2]), __float2half_rn(acc[mt][nt][3]));
            }
        } else {
#pragma unroll
            for (int nt = 0; nt < 4; nt++) {
                int j = n0 - 3072 + wn * 32 + nt * 8 + t4 * 2;
                float b0 = mlpb[j], b1 = mlpb[j + 1];
                if (ok0) {
                    __half u0 = __float2half_rn(gelu1(acc[mt][nt][0] + b0));
                    __half u1 = __float2half_rn(gelu1(acc[mt][nt][1] + b1));
                    *(uint32_t*)(g_h + (size_t)tk0 * CINC + 1024 + j) = pack_h2(u0, u1);
                }
                if (ok1) {
                    __half u0 = __float2half_rn(gelu1(acc[mt][nt][2] + b0));
                    __half u1 = __float2half_rn(gelu1(acc[mt][nt][3] + b1));
                    *(uint32_t*)(g_h + (size_t)tk1 * CINC + 1024 + j) = pack_h2(u0, u1);
                }
            }
        }
    }
}

// ---------------------------------------------------------------------------
// Contract GEMM fused with final epilogue. Single barrier per K-chunk.
// ---------------------------------------------------------------------------
__global__ void __launch_bounds__(256, 2)
contract_kernel(const float* __restrict__ x, const float* __restrict__ rp,
                const float* __restrict__ cb, const float* __restrict__ alpha,
                float* __restrict__ out) {
    const int e = blockIdx.z;
    const bool E3 = (e == 3);
    if (!E3 && blockIdx.x >= 8) return;
    const int cnt  = g_cnt[e];
    const int goff = g_goff[e];
    const int m0 = blockIdx.y * 128;
    if (m0 >= cnt) return;
    const int dout = 256 << e;
    const int d0 = E3 ? blockIdx.x * 64 : blockIdx.x * 128;

    extern __shared__ char smem_raw[];
    uint32_t sb0 = smem_u32(smem_raw);
    uint32_t pad = ((sb0 + 1023u) & ~1023u) - sb0;
    char* gb = smem_raw + pad;
    uint32_t sb = sb0 + pad + 1024u;
    int* tok = (int*)gb;

    const int tid  = threadIdx.x;
    const int lane = tid & 31;
    const int wid  = tid >> 5;
    const int wm = wid & 1;
    const int wn = wid >> 1;

    if (tid < 128) {
        int gr = m0 + tid;
        tok[tid] = g_perm[goff + ((gr < cnt) ? gr : 0)];
    }
    __syncthreads();

    if (!E3 && d0 >= dout) {
#pragma unroll
        for (int it = 0; it < 16; it++) {
            int i = tid + it * 256;
            int r = i >> 5, c4 = i & 31;
            if (m0 + r < cnt) {
                int tk = tok[r];
                *(float4*)(out + (size_t)tk * DIMC + d0 + c4 * 4) =
                    *(const float4*)(x + (size_t)tk * DIMC + d0 + c4 * 4);
            }
        }
        return;
    }

    const int NC = CINC / 64;   // 80

    auto load_chunk = [&](int c) {
        uint32_t bufb = sb + (uint32_t)(c % 3) * GBUF;
        int k0 = c * 64;
#pragma unroll
        for (int it = 0; it < 4; it++) {
            int i = tid + it * 256;
            int r = i >> 3, kg = i & 7;
            const __half* src = g_h + (size_t)tok[r] * CINC + k0 + kg * 8;
            cpa16(bufb + GOA + SWZ(r * 128 + kg * 16), src);
        }
#pragma unroll
        for (int it = 0; it < 4; it++) {
            int i = tid + it * 256;
            int r = i >> 3, kg = i & 7;
            int rowg = (E3 && r >= 64) ? (960 + d0 + r) : (d0 + r);
            const __half* src = g_wc + (size_t)rowg * CINC + k0 + kg * 8;
            cpa16(bufb + GOB + SWZ(r * 128 + kg * 16), src);
        }
        CP_COMMIT();
    };

    load_chunk(0);
    load_chunk(1);

    float acc[4][4][4];
#pragma unroll
    for (int i = 0; i < 4; i++)
#pragma unroll
        for (int j = 0; j < 4; j++)
#pragma unroll
            for (int k = 0; k < 4; k++) acc[i][j][k] = 0.f;

    const int a_r16 = lane & 15;
    const int a_kb  = (lane >> 4) * 16;
    const int b_r8  = ((lane >> 4) << 3) + (lane & 7);
    const int b_kb  = ((lane >> 3) & 1) * 16;

    for (int c = 0; c < NC; c++) {
        if (c < NC - 1) CP_WAIT1(); else CP_WAIT0();
        __syncthreads();
        if (c + 2 < NC) load_chunk(c + 2);

        uint32_t bufb = sb + (uint32_t)(c % 3) * GBUF;
#pragma unroll
        for (int kk = 0; kk < 4; kk++) {
            int kb = kk * 32;
            uint32_t ah[4][4];
#pragma unroll
            for (int mt = 0; mt < 4; mt++) {
                int r = wm * 64 + mt * 16 + a_r16;
                uint32_t off = (uint32_t)(r * 128) + (uint32_t)((kb + a_kb) ^ ((r & 7) << 4));
                ldsm4(ah[mt], bufb + GOA + off);
            }
#pragma unroll
            for (int ntp = 0; ntp < 2; ntp++) {
                int r = wn * 32 + ntp * 16 + b_r8;
                uint32_t off = (uint32_t)(r * 128) + (uint32_t)((kb + b_kb) ^ ((r & 7) << 4));
                uint32_t bf[4];
                ldsm4(bf, bufb + GOB + off);
#pragma unroll
                for (int mt = 0; mt < 4; mt++) {
                    mma16816h(acc[mt][2 * ntp],     ah[mt], bf);
                    mma16816h(acc[mt][2 * ntp + 1], ah[mt], bf + 2);
                }
            }
        }
    }

    const int g = lane >> 2, t4 = lane & 3;

    if (!E3) {
#pragma unroll
        for (int mt = 0; mt < 4; mt++) {
            int r0 = wm * 64 + mt * 16 + g;
            int r1 = r0 + 8;
            int tk0 = tok[r0], tk1 = tok[r1];
            bool ok0 = (m0 + r0) < cnt, ok1 = (m0 + r1) < cnt;
#pragma unroll
            for (int nt = 0; nt < 4; nt++) {
                int d = d0 + wn * 32 + nt * 8 + t4 * 2;
                float c0 = cb[d], c1 = cb[d + 1];
                if (ok0) {
                    float2 xv = *(const float2*)(x + (size_t)tk0 * DIMC + d);
                    *(float2*)(out + (size_t)tk0 * DIMC + d) =
                        make_float2(xv.x + acc[mt][nt][0] + c0, xv.y + acc[mt][nt][1] + c1);
                }
                if (ok1) {
                    float2 xv = *(const float2*)(x + (size_t)tk1 * DIMC + d);
                    *(float2*)(out + (size_t)tk1 * DIMC + d) =
                        make_float2(xv.x + acc[mt][nt][2] + c0, xv.y + acc[mt][nt][3] + c1);
                }
            }
        }
    } else {
        float* zbuf = (float*)(gb + 1024);
        float av = alpha[0];
        __syncthreads();   // all warps past last ldsm before zbuf overwrites stage smem
        if (wn >= 2) {
#pragma unroll
            for (int mt = 0; mt < 4; mt++) {
                int r0 = wm * 64 + mt * 16 + g;
#pragma unroll
                for (int nt = 0; nt < 4; nt++) {
                    int c = (wn - 2) * 32 + nt * 8 + t4 * 2;
                    float c0 = cb[1024 + d0 + c], c1 = cb[1024 + d0 + c + 1];
                    zbuf[r0 * 65 + c]           = acc[mt][nt][0] + c0;
                    zbuf[r0 * 65 + c + 1]       = acc[mt][nt][1] + c1;
                    zbuf[(r0 + 8) * 65 + c]     = acc[mt][nt][2] + c0;
                    zbuf[(r0 + 8) * 65 + c + 1] = acc[mt][nt][3] + c1;
                }
            }
        }
        __syncthreads();
        if (wn < 2) {
#pragma unroll
            for (int mt = 0; mt < 4; mt++) {
                int r0 = wm * 64 + mt * 16 + g;
                int r1 = r0 + 8;
                int tk0 = tok[r0], tk1 = tok[r1];
                bool ok0 = (m0 + r0) < cnt, ok1 = (m0 + r1) < cnt;
                float s0 = ok0 ? (av * rp[tk0 * 4 + 3] + 1.f) : 0.f;
                float s1 = ok1 ? (av * rp[tk1 * 4 + 3] + 1.f) : 0.f;
#pragma unroll
                for (int nt = 0; nt < 4; nt++) {
                    int c = wn * 32 + nt * 8 + t4 * 2;
                    int d = d0 + c;
                    float c0 = cb[d], c1 = cb[d + 1];
                    if (ok0) {
                        float2 xv = *(const float2*)(x + (size_t)tk0 * DIMC + d);
                        float zm0 = zbuf[r0 * 65 + c], zm1 = zbuf[r0 * 65 + c + 1];
                        *(float2*)(out + (size_t)tk0 * DIMC + d) =
                            make_float2(xv.x + acc[mt][nt][0] + c0 + s0 * zm0,
                                        xv.y + acc[mt][nt][1] + c1 + s0 * zm1);
                    }
                    if (ok1) {
                        float2 xv = *(const float2*)(x + (size_t)tk1 * DIMC + d);
                        float zm0 = zbuf[r1 * 65 + c], zm1 = zbuf[r1 * 65 + c + 1];
                        *(float2*)(out + (size_t)tk1 * DIMC + d) =
                            make_float2(xv.x + acc[mt][nt][2] + c0 + s1 * zm0,
                                        xv.y + acc[mt][nt][3] + c1 + s1 * zm1);
                    }
                }
            }
        }
    }
}

// ---------------------------------------------------------------------------
// Flash attention (all single fp16), 3-stage KV pipeline, single barrier/tile.
// smem: Q 16KB + 3*16KB stages = 65.5 KB, 2 CTAs/SM.
// ---------------------------------------------------------------------------
#define FQ  0
#define FST 16384
#define FSS 16384
#define FSM (16384 + 3 * 16384 + 1024)   // 66560

__global__ void __launch_bounds__(256, 2)
flash_kernel() {
    extern __shared__ char smem_raw[];
    uint32_t sb = smem_u32(smem_raw);
    sb = (sb + 1023u) & ~1023u;

    const int tid  = threadIdx.x;
    const int wid  = tid >> 5;
    const int lane = tid & 31;
    const int bh = blockIdx.y;
    const int q0 = blockIdx.x * 128;
    const int b = bh >> 4, h = bh & 15;

    const size_t base = (size_t)bh * SEQC * HDC;

    auto load_q = [&]() {
#pragma unroll
        for (int it = 0; it < 4; it++) {
            int i = tid + it * 256;
            int r = i >> 3, kg = i & 7;
            const __half* src = g_q + base + (size_t)(q0 + r) * HDC + kg * 8;
            cpa16(sb + FQ + SWZ(r * 128 + kg * 16), src);
        }
    };
    auto load_kv = [&](int t) {
        uint32_t bufb = sb + FST + (uint32_t)(t % 3) * FSS;
#pragma unroll
        for (int it = 0; it < 2; it++) {
            int i = tid + it * 256;
            int r = i >> 3, kg = i & 7;
            const __half* src = g_k + base + (size_t)(t * 64 + r) * HDC + kg * 8;
            cpa16(bufb + SWZ(r * 128 + kg * 16), src);
        }
#pragma unroll
        for (int it = 0; it < 2; it++) {
            int i = tid + it * 256;
            int r = i >> 3, kg = i & 7;
            const __half* src = g_v + base + (size_t)(t * 64 + r) * HDC + kg * 8;
            cpa16(bufb + 8192 + SWZ(r * 128 + kg * 16), src);
        }
        CP_COMMIT();
    };

    load_q(); load_kv(0); CP_COMMIT();   // group: Q+stage0
    load_kv(1);

    const int a_r16 = lane & 15;
    const int a_kb  = (lane >> 4) * 16;
    const int b_r8  = ((lane >> 4) << 3) + (lane & 7);
    const int b_kb  = ((lane >> 3) & 1) * 16;
    const int v_r  = ((lane >> 3) & 1) * 8 + (lane & 7);
    const int v_cb = (lane >> 4) * 16;

    uint32_t qf[4][4];
    float o[8][4];
#pragma unroll
    for (int j = 0; j < 8; j++)
#pragma unroll
        for (int k = 0; k < 4; k++) o[j][k] = 0.f;
    float ml0 = -1e30f, ml1 = -1e30f, ls0 = 0.f, ls1 = 0.f;

    for (int t = 0; t < 16; t++) {
        if (t < 15) CP_WAIT1(); else CP_WAIT0();
        __syncthreads();
        if (t + 2 < 16) load_kv(t + 2);
        if (t == 0) {
#pragma unroll
            for (int kk = 0; kk < 4; kk++) {
                int r = wid * 16 + a_r16;
                uint32_t off = (uint32_t)(r * 128) + (uint32_t)((kk * 32 + a_kb) ^ ((r & 7) << 4));
                ldsm4(qf[kk], sb + FQ + off);
            }
        }
        uint32_t bufb = sb + FST + (uint32_t)(t % 3) * FSS;

        float s[8][4];
#pragma unroll
        for (int j = 0; j < 8; j++)
#pragma unroll
            for (int k = 0; k < 4; k++) s[j][k] = 0.f;
#pragma unroll
        for (int kk = 0; kk < 4; kk++) {
#pragma unroll
            for (int ntp = 0; ntp < 4; ntp++) {
                int r = ntp * 16 + b_r8;
                uint32_t off = (uint32_t)(r * 128) + (uint32_t)((kk * 32 + b_kb) ^ ((r & 7) << 4));
                uint32_t kf[4];
                ldsm4(kf, bufb + off);
                mma16816h(s[2 * ntp],     qf[kk], kf);
                mma16816h(s[2 * ntp + 1], qf[kk], kf + 2);
            }
        }

        float m0t = -1e30f, m1t = -1e30f;
#pragma unroll
        for (int j = 0; j < 8; j++) {
            m0t = fmaxf(m0t, fmaxf(s[j][0], s[j][1]));
            m1t = fmaxf(m1t, fmaxf(s[j][2], s[j][3]));
        }
        m0t = fmaxf(m0t, __shfl_xor_sync(0xffffffffu, m0t, 1));
        m0t = fmaxf(m0t, __shfl_xor_sync(0xffffffffu, m0t, 2));
        m1t = fmaxf(m1t, __shfl_xor_sync(0xffffffffu, m1t, 1));
        m1t = fmaxf(m1t, __shfl_xor_sync(0xffffffffu, m1t, 2));
        float mn0 = fmaxf(ml0, m0t), mn1 = fmaxf(ml1, m1t);
        float sc0 = exp2f(ml0 - mn0), sc1 = exp2f(ml1 - mn1);
        ml0 = mn0; ml1 = mn1;
        float r0 = 0.f, r1 = 0.f;
#pragma unroll
        for (int j = 0; j < 8; j++) {
            s[j][0] = exp2f(s[j][0] - mn0);
            s[j][1] = exp2f(s[j][1] - mn0);
            s[j][2] = exp2f(s[j][2] - mn1);
            s[j][3] = exp2f(s[j][3] - mn1);
            r0 += s[j][0] + s[j][1];
            r1 += s[j][2] + s[j][3];
        }
        r0 += __shfl_xor_sync(0xffffffffu, r0, 1);
        r0 += __shfl_xor_sync(0xffffffffu, r0, 2);
        r1 += __shfl_xor_sync(0xffffffffu, r1, 1);
        r1 += __shfl_xor_sync(0xffffffffu, r1, 2);
        ls0 = ls0 * sc0 + r0;
        ls1 = ls1 * sc1 + r1;
#pragma unroll
        for (int j = 0; j < 8; j++) {
            o[j][0] *= sc0; o[j][1] *= sc0;
            o[j][2] *= sc1; o[j][3] *= sc1;
        }

        uint32_t pa[4][4];
#pragma unroll
        for (int kt = 0; kt < 4; kt++) {
            pa[kt][0] = pack_h2(__float2half_rn(s[2 * kt][0]),     __float2half_rn(s[2 * kt][1]));
            pa[kt][1] = pack_h2(__float2half_rn(s[2 * kt][2]),     __float2half_rn(s[2 * kt][3]));
            pa[kt][2] = pack_h2(__float2half_rn(s[2 * kt + 1][0]), __float2half_rn(s[2 * kt + 1][1]));
            pa[kt][3] = pack_h2(__float2half_rn(s[2 * kt + 1][2]), __float2half_rn(s[2 * kt + 1][3]));
        }

#pragma unroll
        for (int kt = 0; kt < 4; kt++) {
#pragma unroll
            for (int nv = 0; nv < 4; nv++) {
                int r = kt * 16 + v_r;
                uint32_t off = (uint32_t)(r * 128) + (uint32_t)((nv * 32 + v_cb) ^ ((r & 7) << 4));
                uint32_t vf[4];
                ldsm4t(vf, bufb + 8192 + off);
                mma16816h(o[2 * nv],     pa[kt], vf);
                mma16816h(o[2 * nv + 1], pa[kt], vf + 2);
            }
        }
    }

    const int g = lane >> 2, t4 = lane & 3;
    float i0 = 1.f / ls0, i1 = 1.f / ls1;
    int tok0 = b * 1024 + q0 + wid * 16 + g;
    int tok1 = tok0 + 8;
#pragma unroll
    for (int j = 0; j < 8; j++) {
        int col = h * 64 + j * 8 + t4 * 2;
        *(uint32_t*)(g_h + (size_t)tok0 * CINC + col) =
            pack_h2(__float2half_rn(o[j][0] * i0), __float2half_rn(o[j][1] * i0));
        *(uint32_t*)(g_h + (size_t)tok1 * CINC + col) =
            pack_h2(__float2half_rn(o[j][2] * i1), __float2half_rn(o[j][3] * i1));
    }
}

// ---------------------------------------------------------------------------
// Expert permutation (single CTA) + pass-through output tails
// ---------------------------------------------------------------------------
__global__ void __launch_bounds__(1024) perm_kernel(const int* __restrict__ em,
                                                    const float* __restrict__ rp,
                                                    float* __restrict__ out) {
    __shared__ int cnt[4], off[4], cur[4];
    int tid = threadIdx.x;
    if (tid < 4) { cnt[tid] = 0; cur[tid] = 0; }
    __syncthreads();
    int ev[8];
#pragma unroll
    for (int i = 0; i < 8; i++) {
        ev[i] = em[tid + i * 1024];
        atomicAdd(&cnt[ev[i]], 1);
    }
    __syncthreads();
    if (tid == 0) {
        int o = 0;
        for (int j = 0; j < 4; j++) { off[j] = o; g_goff[j] = o; g_cnt[j] = cnt[j]; o += cnt[j]; }
    }
    __syncthreads();
#pragma unroll
    for (int i = 0; i < 8; i++) {
        int p = atomicAdd(&cur[ev[i]], 1);
        g_perm[off[ev[i]] + p] = tid + i * 1024;
        out[(size_t)TOK * DIMC + tid + i * 1024] = (float)ev[i];
    }
#pragma unroll
    for (int i = 0; i < 32; i++) {
        int j = tid + i * 1024;
        out[(size_t)TOK * DIMC + TOK + j] = rp[j];
    }
}

// merged weight convert (fp32 -> fp16)
#define NW1 ((EXPC * DIMC) / 4)
__global__ void convw_kernel(const float* __restrict__ we, const float* __restrict__ wc,
                             __half* __restrict__ dwe, __half* __restrict__ dwc) {
    size_t i = (size_t)blockIdx.x * 256 + threadIdx.x;
    const float* s; __half* d; size_t j;
    if (i < NW1) { s = we; d = dwe; j = i; }
    else         { s = wc; d = dwc; j = i - NW1; }
    float4 v = ((const float4*)s)[j];
    ((uint32_t*)d)[2 * j]     = pack_h2(__float2half_rn(v.x), __float2half_rn(v.y));
    ((uint32_t*)d)[2 * j + 1] = pack_h2(__float2half_rn(v.z), __float2half_rn(v.w));
}

// LN1, warp-per-token. grid TOK/8, block 256.
__global__ void __launch_bounds__(256)
ln1_kernel(const float* __restrict__ x, const int* __restrict__ em,
           const float* __restrict__ g, const float* __restrict__ b) {
    int wid = threadIdx.x >> 5, lane = threadIdx.x & 31;
    int t = blockIdx.x * 8 + wid;
    const float4* xr = (const float4*)(x + (size_t)t * DIMC);
    float4 v[8];
    float s = 0.f, s2 = 0.f;
#pragma unroll
    for (int i = 0; i < 8; i++) {
        v[i] = xr[i * 32 + lane];
        s  += v[i].x + v[i].y + v[i].z + v[i].w;
        s2 += v[i].x * v[i].x + v[i].y * v[i].y + v[i].z * v[i].z + v[i].w * v[i].w;
    }
#pragma unroll
    for (int o = 16; o; o >>= 1) { s += __shfl_xor_sync(0xffffffffu, s, o); s2 += __shfl_xor_sync(0xffffffffu, s2, o); }
    float m = s * (1.f / DIMC);
    float rs = rsqrtf(s2 * (1.f / DIMC) - m * m + 1e-5f);
    int din = DIMC >> (3 - em[t]);
#pragma unroll
    for (int i = 0; i < 8; i++) {
        int c = i * 128 + lane * 4;
        float4 gg = ((const float4*)g)[i * 32 + lane];
        float4 bb = ((const float4*)b)[i * 32 + lane];
        float o0 = (c + 0 < din) ? ((v[i].x - m) * rs * gg.x + bb.x) : 0.f;
        float o1 = (c + 1 < din) ? ((v[i].y - m) * rs * gg.y + bb.y) : 0.f;
        float o2 = (c + 2 < din) ? ((v[i].z - m) * rs * gg.z + bb.z) : 0.f;
        float o3 = (c + 3 < din) ? ((v[i].w - m) * rs * gg.w + bb.w) : 0.f;
        size_t o = (size_t)t * DIMC + c;
        *(uint32_t*)(g_xn + o)     = pack_h2(__float2half_rn(o0), __float2half_rn(o1));
        *(uint32_t*)(g_xn + o + 2) = pack_h2(__float2half_rn(o2), __float2half_rn(o3));
    }
}

// LN2 warp-per-row: which==0 -> k, which==1 -> v. grid (TOK/8, 2), block 256.
__global__ void __launch_bounds__(256)
ln2kv_kernel(const float* __restrict__ g, const float* __restrict__ b) {
    int wid = threadIdx.x >> 5, lane = threadIdx.x & 31;
    int t = blockIdx.x * 8 + wid;
    int which = blockIdx.y;
    const __half* row = g_yh + (size_t)t * 2048 + (size_t)DIMC * which;
    float4 v[8];
    float s = 0.f, s2 = 0.f;
#pragma unroll
    for (int i = 0; i < 8; i++) {
        uint2 raw = *(const uint2*)(row + i * 128 + lane * 4);
        __half2 p0 = *(__half2*)&raw.x;
        __half2 p1 = *(__half2*)&raw.y;
        v[i] = make_float4(__half2float(p0.x), __half2float(p0.y),
                           __half2float(p1.x), __half2float(p1.y));
        s  += v[i].x + v[i].y + v[i].z + v[i].w;
        s2 += v[i].x * v[i].x + v[i].y * v[i].y + v[i].z * v[i].z + v[i].w * v[i].w;
    }
#pragma unroll
    for (int o = 16; o; o >>= 1) { s += __shfl_xor_sync(0xffffffffu, s, o); s2 += __shfl_xor_sync(0xffffffffu, s2, o); }
    float m = s * (1.f / DIMC);
    float rs = rsqrtf(s2 * (1.f / DIMC) - m * m + 1e-5f);
    int bb2 = t >> 10, ss = t & 1023;
    __half* d = which ? g_v : g_k;
#pragma unroll
    for (int i = 0; i < 8; i++) {
        int c = i * 128 + lane * 4;
        float4 gg = ((const float4*)g)[i * 32 + lane];
        float4 bv = ((const float4*)b)[i * 32 + lane];
        float o0 = (v[i].x - m) * rs * gg.x + bv.x;
        float o1 = (v[i].y - m) * rs * gg.y + bv.y;
        float o2 = (v[i].z - m) * rs * gg.z + bv.z;
        float o3 = (v[i].w - m) * rs * gg.w + bv.w;
        int hh = c >> 6, hd = c & 63;
        size_t o = ((size_t)(bb2 * NHC + hh) * SEQC + ss) * HDC + hd;
        *(uint32_t*)(d + o)     = pack_h2(__float2half_rn(o0), __float2half_rn(o1));
        *(uint32_t*)(d + o + 2) = pack_h2(__float2half_rn(o2), __float2half_rn(o3));
    }
}

// ---------------------------------------------------------------------------
extern "C" void kernel_launch(void* const* d_in, const int* in_sizes, int n_in,
                              void* d_out, int out_size) {
    const float* x     = (const float*)d_in[0];
    const int*   em    = (const int*)d_in[1];
    const float* rp    = (const float*)d_in[2];
    const float* wexp  = (const float*)d_in[3];
    const float* mlpb  = (const float*)d_in[4];
    const float* wc    = (const float*)d_in[5];
    const float* cb    = (const float*)d_in[6];
    const float* n1g   = (const float*)d_in[7];
    const float* n1b   = (const float*)d_in[8];
    const float* n2g   = (const float*)d_in[9];
    const float* n2b   = (const float*)d_in[10];
    const float* alpha = (const float*)d_in[11];
    float* out = (float*)d_out;

    __half *p_we, *p_wc;
    cudaGetSymbolAddress((void**)&p_we, g_we);
    cudaGetSymbolAddress((void**)&p_wc, g_wc);

    cudaFuncSetAttribute(expand_kernel,   cudaFuncAttributeMaxDynamicSharedMemorySize, GSM);
    cudaFuncSetAttribute(contract_kernel, cudaFuncAttributeMaxDynamicSharedMemorySize, GSM);
    cudaFuncSetAttribute(flash_kernel,    cudaFuncAttributeMaxDynamicSharedMemorySize, FSM);

    // 0) expert permutation + pass-through tails
    perm_kernel<<<1, 1024>>>(em, rp, out);

    // 0b) weight converts (merged)
    convw_kernel<<<(NW1 + (2 * DIMC * CINC) / 4) / 256, 256>>>(wexp, wc, p_we, p_wc);

    // 1) LN1 + input mask -> xn fp16 (warp per token)
    ln1_kernel<<<TOK / 8, 256>>>(x, em, n1g, n1b);

    // 2) expand (grouped, heavy experts first)
    expand_kernel<<<dim3(EXPC / 128, TOK / 128, 4), 256, GSM>>>(mlpb);

    // 3) LN2 -> k and v per-head fp16 (warp per row)
    ln2kv_kernel<<<dim3(TOK / 8, 2), 256>>>(n2g, n2b);

    // 4) flash attention -> g_h fp16 [:, 0:1024]
    flash_kernel<<<dim3(SEQC / 128, BH), 256, FSM>>>();

    // 5) contract fused with final epilogue -> out
    contract_kernel<<<dim3(16, TOK / 128, 4), 256, GSM>>>(x, rp, cb, alpha, out);
}